// round 10
// baseline (speedup 1.0000x reference)
#include <cuda_runtime.h>
#include <cuda_bf16.h>
#include <cstdint>

#define NN 16384
#define DH 128
#define TT 256
#define QSCALE (0.08838834764831845f * 1.4426950408889634f)  // 1/sqrt(128) * log2(e)

#define BM 64
#define BN 128
#define NT (NN / BN)

// smem layout (bytes)
#define KS_STRIDE 272                      // 128 bf16 + 16B pad
#define HS_STRIDE 528                      // 256 bf16 + 16B pad
#define PS_STRIDE 272
#define KBYTES (128 * KS_STRIDE)           // 34816 (single buffer, S-group)
#define HBYTES (128 * HS_STRIDE)           // 67584 (x2, O-group)
#define PBYTES (64 * PS_STRIDE)            // 17408 (x2)
#define OFF_K 0
#define OFF_H KBYTES                       // 34816, stages at +0 / +HBYTES
#define OFF_P (OFF_H + 2 * HBYTES)         // 169984, stages at +0 / +PBYTES
#define OFF_L (OFF_P + 2 * PBYTES)         // 204800
#define ATTN_SMEM (OFF_L + 1024)           // 205824

// device-global scratch (allocation-guard safe)
__device__ __nv_bfloat16 g_Qb[NN * DH];          // Q*QSCALE bf16
__device__ __nv_bfloat16 g_Kb[NN * DH];          // K bf16
__device__ __nv_bfloat16 g_Hb[(size_t)NN * TT];  // H bf16

// ===========================================================================
// helpers (sm_80-baseline PTX: portable under compute_103)
// ===========================================================================
__device__ __forceinline__ uint32_t smem_u32(const void* p) {
    uint32_t a;
    asm("{ .reg .u64 t; cvta.to.shared.u64 t, %1; cvt.u32.u64 %0, t; }"
        : "=r"(a) : "l"(p));
    return a;
}
__device__ __forceinline__ void ldsm_x4(uint32_t& r0, uint32_t& r1,
                                        uint32_t& r2, uint32_t& r3, uint32_t a) {
    asm volatile("ldmatrix.sync.aligned.m8n8.x4.shared.b16 {%0,%1,%2,%3}, [%4];"
                 : "=r"(r0), "=r"(r1), "=r"(r2), "=r"(r3) : "r"(a));
}
__device__ __forceinline__ void ldsm_x4_t(uint32_t& r0, uint32_t& r1,
                                          uint32_t& r2, uint32_t& r3, uint32_t a) {
    asm volatile("ldmatrix.sync.aligned.m8n8.x4.trans.shared.b16 {%0,%1,%2,%3}, [%4];"
                 : "=r"(r0), "=r"(r1), "=r"(r2), "=r"(r3) : "r"(a));
}
__device__ __forceinline__ void mma16816(float* d, const uint32_t* a,
                                         uint32_t b0, uint32_t b1) {
    asm volatile("mma.sync.aligned.m16n8k16.row.col.f32.bf16.bf16.f32 "
                 "{%0,%1,%2,%3},{%4,%5,%6,%7},{%8,%9},{%0,%1,%2,%3};"
                 : "+f"(d[0]), "+f"(d[1]), "+f"(d[2]), "+f"(d[3])
                 : "r"(a[0]), "r"(a[1]), "r"(a[2]), "r"(a[3]), "r"(b0), "r"(b1));
}
__device__ __forceinline__ void cp16(uint32_t dst, const void* src) {
    asm volatile("cp.async.cg.shared.global [%0], [%1], 16;"
                 :: "r"(dst), "l"(src) : "memory");
}
__device__ __forceinline__ void cp_commit() {
    asm volatile("cp.async.commit_group;" ::: "memory");
}
__device__ __forceinline__ void cp_wait0() {
    asm volatile("cp.async.wait_group 0;" ::: "memory");
}
__device__ __forceinline__ void cp_wait1() {
    asm volatile("cp.async.wait_group 1;" ::: "memory");
}
__device__ __forceinline__ float ex2f(float x) {
    float y;
    asm("ex2.approx.f32 %0, %1;" : "=f"(y) : "f"(x));
    return y;
}
__device__ __forceinline__ uint32_t packbf2(float lo, float hi) {
    __nv_bfloat162 v = __floats2bfloat162_rn(lo, hi);
    return *(uint32_t*)&v;
}
__device__ __forceinline__ void bar_s(int id, int cnt) {
    asm volatile("bar.sync %0, %1;" :: "r"(id), "r"(cnt) : "memory");
}
__device__ __forceinline__ void bar_a(int id, int cnt) {
    asm volatile("bar.arrive %0, %1;" :: "r"(id), "r"(cnt) : "memory");
}
__device__ __forceinline__ void fence_cta() {
    asm volatile("membar.cta;" ::: "memory");
}

// ===========================================================================
// Kernel 1: Q = (H Wq + bq)*QSCALE -> bf16 ; K = H Wk + bk -> bf16 (2 CTA/SM)
// ===========================================================================
__global__ void __launch_bounds__(256, 2)
qk_kernel(const float* __restrict__ H,
          const float* __restrict__ Wq, const float* __restrict__ bq,
          const float* __restrict__ Wk, const float* __restrict__ bk) {
    __shared__ float HsT[32 * 129];
    __shared__ float Ws[32 * 128];

    const float* W = blockIdx.y ? Wk : Wq;
    const float* b = blockIdx.y ? bk : bq;
    __nv_bfloat16* outp = blockIdx.y ? g_Kb : g_Qb;
    const float osc = blockIdx.y ? 1.0f : QSCALE;

    const int tid = threadIdx.x;
    const int ty = tid >> 4, tx = tid & 15;
    const int row0 = blockIdx.x * 128;

    float acc[8][8];
    #pragma unroll
    for (int i = 0; i < 8; i++)
        #pragma unroll
        for (int j = 0; j < 8; j++) acc[i][j] = 0.f;

    for (int kc = 0; kc < TT; kc += 32) {
        __syncthreads();
        #pragma unroll
        for (int idx = tid; idx < 128 * 32; idx += 256) {
            int r = idx >> 5, k = idx & 31;
            HsT[k * 129 + r] = H[(size_t)(row0 + r) * TT + kc + k];
        }
        #pragma unroll
        for (int idx = tid; idx < 32 * 128; idx += 256) {
            int k = idx >> 7, c = idx & 127;
            Ws[k * 128 + c] = W[(size_t)(kc + k) * DH + c];
        }
        __syncthreads();
        #pragma unroll 4
        for (int k = 0; k < 32; k++) {
            float h[8], w[8];
            #pragma unroll
            for (int i = 0; i < 8; i++) h[i] = HsT[k * 129 + ty * 8 + i];
            float4 w0 = *(const float4*)&Ws[k * 128 + tx * 8];
            float4 w1 = *(const float4*)&Ws[k * 128 + tx * 8 + 4];
            w[0]=w0.x; w[1]=w0.y; w[2]=w0.z; w[3]=w0.w;
            w[4]=w1.x; w[5]=w1.y; w[6]=w1.z; w[7]=w1.w;
            #pragma unroll
            for (int i = 0; i < 8; i++)
                #pragma unroll
                for (int j = 0; j < 8; j++)
                    acc[i][j] += h[i] * w[j];
        }
    }

    float bb[8];
    {
        float4 b0 = *(const float4*)&b[tx * 8];
        float4 b1 = *(const float4*)&b[tx * 8 + 4];
        bb[0]=b0.x; bb[1]=b0.y; bb[2]=b0.z; bb[3]=b0.w;
        bb[4]=b1.x; bb[5]=b1.y; bb[6]=b1.z; bb[7]=b1.w;
    }
    #pragma unroll
    for (int i = 0; i < 8; i++) {
        int r = row0 + ty * 8 + i;
        __nv_bfloat16 t8[8];
        #pragma unroll
        for (int j = 0; j < 8; j++)
            t8[j] = __float2bfloat16((acc[i][j] + bb[j]) * osc);
        *(uint4*)&outp[(size_t)r * DH + tx * 8] = *(const uint4*)t8;
    }
}

// ===========================================================================
// Kernel 2: H -> bf16
// ===========================================================================
__global__ __launch_bounds__(256)
void hconv_kernel(const float* __restrict__ H) {
    size_t i = (size_t)blockIdx.x * 256 + threadIdx.x;
    float4 v = ((const float4*)H)[i];
    __nv_bfloat162 a = __floats2bfloat162_rn(v.x, v.y);
    __nv_bfloat162 b = __floats2bfloat162_rn(v.z, v.w);
    uint2 o;
    o.x = *(uint32_t*)&a;
    o.y = *(uint32_t*)&b;
    ((uint2*)g_Hb)[i] = o;
}

// ===========================================================================
// Kernel 3: warp-specialized flash attention. 384 threads.
// S-group (warps 0-3, threads 0-127): MMA1 + exp + P STS + l-sums.
//   warp = (wr = wid>>1: 32 q-rows) x (kh = wid&1: 64-key slice). K single-buf.
// O-group (warps 4-11, threads 128-383): MMA2 over full 128 keys.
//   warp ow = wid-4: rows (ow>>2)*32, cols (ow&3)*64. H double-buf (O-owned).
// P double-buffered; handshake: full[s]=bar 3+s, empty[s]=bar 5+s (count 384).
// ===========================================================================
__global__ __launch_bounds__(384, 1)
void attn10_kernel(const float* __restrict__ H, float* __restrict__ out) {
    extern __shared__ char sm[];
    const uint32_t sb = smem_u32(sm);
    const int tid = threadIdx.x;
    const int wid = tid >> 5, lane = tid & 31;
    const int g = lane >> 2, t = lane & 3;
    const int bl = lane >> 3, rl = lane & 7;
    const int q0 = blockIdx.x * BM;
    const bool isS = (wid < 4);

    // ---- prologue: launch tile-0 loads (group-private), stage Q ----
    if (isS) {
        #pragma unroll 4
        for (int i = tid; i < 2048; i += 128) {           // K(0): 32KB
            int r = i >> 4, c = i & 15;
            cp16(sb + OFF_K + r * KS_STRIDE + c * 16,
                 (const char*)g_Kb + (size_t)r * 256 + c * 16);
        }
        cp_commit();
    } else {
        int tO = tid - 128;
        #pragma unroll 4
        for (int i = tO; i < 4096; i += 256) {            // H(0): 64KB -> stage 0
            int r = i >> 5, c = i & 31;
            cp16(sb + OFF_H + r * HS_STRIDE + c * 16,
                 (const char*)g_Hb + (size_t)r * 512 + c * 16);
        }
        cp_commit();
    }
    for (int i = tid; i < 1024; i += 384) {               // Q -> P stage0 region
        int r = i >> 4, c = i & 15;
        uint4 v = *(const uint4*)(g_Qb + (size_t)(q0 + r) * DH + c * 8);
        *(uint4*)(sm + OFF_P + r * PS_STRIDE + c * 16) = v;
    }
    __syncthreads();

    float* Ls = (float*)(sm + OFF_L);

    if (isS) {
        // ================= S-group =================
        const int kh = wid & 1, wr = wid >> 1;
        const int nrow = kh * 64 + rl + ((bl & 2) ? 8 : 0);
        const int kc = (bl & 1) ? 16 : 0;

        uint32_t aq[2][8][4];
        #pragma unroll
        for (int mb = 0; mb < 2; mb++) {
            int m = wr * 32 + mb * 16 + rl + ((bl & 1) ? 8 : 0);
            #pragma unroll
            for (int s = 0; s < 8; s++) {
                uint32_t addr = sb + OFF_P + m * PS_STRIDE + s * 32
                              + ((bl & 2) ? 16 : 0);
                ldsm_x4(aq[mb][s][0], aq[mb][s][1], aq[mb][s][2], aq[mb][s][3], addr);
            }
        }

        float lsum[4] = {0.f, 0.f, 0.f, 0.f};
        const int diag_kt = q0 >> 7;

        for (int kt = 0; kt < NT; kt++) {
            cp_wait0();
            bar_s(1, 128);                    // K(kt) complete + visible (S-group)

            // MMA1: S[32 rows, 64-key slice]
            float sacc[2][8][4];
            #pragma unroll
            for (int mb = 0; mb < 2; mb++)
                #pragma unroll
                for (int jj = 0; jj < 8; jj++)
                    #pragma unroll
                    for (int x = 0; x < 4; x++) sacc[mb][jj][x] = 0.f;
            #pragma unroll
            for (int s = 0; s < 8; s++) {
                #pragma unroll
                for (int nb = 0; nb < 4; nb++) {
                    uint32_t addr = sb + OFF_K + (nrow + nb * 16) * KS_STRIDE
                                  + s * 32 + kc;
                    uint32_t b0, b1, b2, b3;
                    ldsm_x4(b0, b1, b2, b3, addr);
                    #pragma unroll
                    for (int mb = 0; mb < 2; mb++) {
                        mma16816(sacc[mb][2 * nb],     aq[mb][s], b0, b1);
                        mma16816(sacc[mb][2 * nb + 1], aq[mb][s], b2, b3);
                    }
                }
            }
            bar_s(1, 128);                    // all S done reading K buf
            if (kt + 1 < NT) {                // prefetch K(kt+1) (single buffer)
                const char* src = (const char*)(g_Kb + (size_t)(kt + 1) * BN * DH);
                #pragma unroll 4
                for (int i = tid; i < 2048; i += 128) {
                    int r = i >> 4, c = i & 15;
                    cp16(sb + OFF_K + r * KS_STRIDE + c * 16, src + r * 256 + c * 16);
                }
                cp_commit();
            }

            // exp (+ diag -> 1) + l-sums, in place
            {
                const bool dt = (kt == diag_kt);
                const int k0 = kt * BN;
                #pragma unroll
                for (int mb = 0; mb < 2; mb++) {
                    const int row0 = wr * 32 + mb * 16 + g;
                    const int grow0 = q0 + row0, grow1 = grow0 + 8;
                    #pragma unroll
                    for (int jj = 0; jj < 8; jj++) {
                        int gcol = k0 + kh * 64 + jj * 8 + 2 * t;
                        float p0 = ex2f(sacc[mb][jj][0]);
                        float p1 = ex2f(sacc[mb][jj][1]);
                        float p2 = ex2f(sacc[mb][jj][2]);
                        float p3 = ex2f(sacc[mb][jj][3]);
                        if (dt) {
                            if (grow0 == gcol)     p0 = 1.f;
                            if (grow0 == gcol + 1) p1 = 1.f;
                            if (grow1 == gcol)     p2 = 1.f;
                            if (grow1 == gcol + 1) p3 = 1.f;
                        }
                        lsum[2 * mb]     += p0 + p1;
                        lsum[2 * mb + 1] += p2 + p3;
                        sacc[mb][jj][0] = p0; sacc[mb][jj][1] = p1;
                        sacc[mb][jj][2] = p2; sacc[mb][jj][3] = p3;
                    }
                }
            }

            if (kt >= 2) bar_s(5 + (kt & 1), 384);   // stage empty (O done kt-2)

            // publish P(kt) -> stage kt&1
            {
                const uint32_t pst = OFF_P + (uint32_t)(kt & 1) * PBYTES;
                #pragma unroll
                for (int mb = 0; mb < 2; mb++) {
                    const int row0 = wr * 32 + mb * 16 + g;
                    #pragma unroll
                    for (int jj = 0; jj < 8; jj++) {
                        int col = kh * 64 + jj * 8 + 2 * t;
                        *(uint32_t*)(sm + pst + row0 * PS_STRIDE + col * 2) =
                            packbf2(sacc[mb][jj][0], sacc[mb][jj][1]);
                        *(uint32_t*)(sm + pst + (row0 + 8) * PS_STRIDE + col * 2) =
                            packbf2(sacc[mb][jj][2], sacc[mb][jj][3]);
                    }
                }
            }
            fence_cta();
            bar_a(3 + (kt & 1), 384);                // stage full
        }

        // l-sums -> smem for O-group epilogue
        #pragma unroll
        for (int i = 0; i < 4; i++) {
            lsum[i] += __shfl_xor_sync(0xffffffffu, lsum[i], 1);
            lsum[i] += __shfl_xor_sync(0xffffffffu, lsum[i], 2);
        }
        if (t == 0) {
            int r = wr * 32 + g;
            Ls[kh * 64 + r]      = lsum[0];
            Ls[kh * 64 + r + 8]  = lsum[1];
            Ls[kh * 64 + r + 16] = lsum[2];
            Ls[kh * 64 + r + 24] = lsum[3];
        }
        fence_cta();
        bar_a(8, 384);                               // Ls ready
    } else {
        // ================= O-group =================
        const int ow = wid - 4;
        const int wo = ow & 3, wr2 = ow >> 2;
        const int am = rl + ((bl & 1) ? 8 : 0);
        const int akc = (bl & 2) ? 16 : 0;
        const int bk = rl + ((bl & 1) ? 8 : 0);
        const int bn = (bl & 2) ? 8 : 0;
        const int tO = tid - 128;

        float oacc[16][4];
        #pragma unroll
        for (int i = 0; i < 16; i++)
            #pragma unroll
            for (int j = 0; j < 4; j++) oacc[i][j] = 0.f;

        for (int kt = 0; kt < NT; kt++) {
            bar_s(2, 256);                 // all O done MMA2(kt-1): old H stage free
            if (kt + 1 < NT) {             // prefetch H(kt+1) into other stage
                const char* src = (const char*)(g_Hb + (size_t)(kt + 1) * BN * TT);
                const uint32_t dst = sb + OFF_H + (uint32_t)((kt + 1) & 1) * HBYTES;
                #pragma unroll 4
                for (int i = tO; i < 4096; i += 256) {
                    int r = i >> 5, c = i & 31;
                    cp16(dst + r * HS_STRIDE + c * 16, src + r * 512 + c * 16);
                }
                cp_commit();
                cp_wait1();                // H(kt) complete (own)
            } else {
                cp_wait0();
            }
            bar_s(2, 256);                 // H(kt) complete + visible (all O)
            bar_s(3 + (kt & 1), 384);      // P(kt) full

            const uint32_t pst = sb + OFF_P + (uint32_t)(kt & 1) * PBYTES;
            const uint32_t hst = sb + OFF_H + (uint32_t)(kt & 1) * HBYTES;

            // MMA2: O[32 rows, 64 cols] += P[32,128] @ H[128, 64-col slice]
            #pragma unroll
            for (int s2 = 0; s2 < 8; s2++) {
                uint32_t pa[2][4];
                #pragma unroll
                for (int mb = 0; mb < 2; mb++) {
                    uint32_t addr = pst + (wr2 * 32 + mb * 16 + am) * PS_STRIDE
                                  + s2 * 32 + akc;
                    ldsm_x4(pa[mb][0], pa[mb][1], pa[mb][2], pa[mb][3], addr);
                }
                const int krow = s2 * 16 + bk;
                #pragma unroll
                for (int jj = 0; jj < 4; jj++) {
                    uint32_t addr = hst + krow * HS_STRIDE
                                  + (wo * 64 + jj * 16 + bn) * 2;
                    uint32_t b0, b1, b2, b3;
                    ldsm_x4_t(b0, b1, b2, b3, addr);
                    #pragma unroll
                    for (int mb = 0; mb < 2; mb++) {
                        mma16816(oacc[mb * 8 + jj * 2],     pa[mb], b0, b1);
                        mma16816(oacc[mb * 8 + jj * 2 + 1], pa[mb], b2, b3);
                    }
                }
            }
            bar_a(5 + (kt & 1), 384);      // P stage empty
        }

        bar_s(8, 384);                     // wait Ls

        // epilogue: out = O/l + H
        #pragma unroll
        for (int mb = 0; mb < 2; mb++) {
            int row0 = wr2 * 32 + mb * 16 + g;
            float invA = 1.f / (Ls[row0] + Ls[64 + row0]);
            float invB = 1.f / (Ls[row0 + 8] + Ls[64 + row0 + 8]);
            int grow0 = q0 + row0;
            #pragma unroll
            for (int jj = 0; jj < 4; jj++) {
                #pragma unroll
                for (int n8 = 0; n8 < 2; n8++) {
                    int col = wo * 64 + jj * 16 + n8 * 8 + 2 * t;
                    const float* oa = oacc[mb * 8 + jj * 2 + n8];
                    float2 h0 = *(const float2*)(H + (size_t)grow0 * TT + col);
                    float2 h1 = *(const float2*)(H + (size_t)(grow0 + 8) * TT + col);
                    float2 o0, o1;
                    o0.x = oa[0] * invA + h0.x;
                    o0.y = oa[1] * invA + h0.y;
                    o1.x = oa[2] * invB + h1.x;
                    o1.y = oa[3] * invB + h1.y;
                    *(float2*)(out + (size_t)grow0 * TT + col) = o0;
                    *(float2*)(out + (size_t)(grow0 + 8) * TT + col) = o1;
                }
            }
        }
    }
}

// ===========================================================================
extern "C" void kernel_launch(void* const* d_in, const int* in_sizes, int n_in,
                              void* d_out, int out_size) {
    const float* H  = (const float*)d_in[0];
    const float* Wq = (const float*)d_in[1];
    const float* bq = (const float*)d_in[2];
    const float* Wk = (const float*)d_in[3];
    const float* bk = (const float*)d_in[4];
    float* out = (float*)d_out;

    cudaFuncSetAttribute(attn10_kernel,
                         cudaFuncAttributeMaxDynamicSharedMemorySize, ATTN_SMEM);

    qk_kernel<<<dim3(NN / 128, 2), 256>>>(H, Wq, bq, Wk, bk);
    hconv_kernel<<<(NN * TT / 4) / 256, 256>>>(H);
    attn10_kernel<<<NN / BM, 384, ATTN_SMEM>>>(H, out);
}

// round 11
// speedup vs baseline: 1.5698x; 1.5698x over previous
#include <cuda_runtime.h>
#include <cuda_bf16.h>
#include <cstdint>

#define NN 16384
#define DH 128
#define TT 256
#define QSCALE (0.08838834764831845f * 1.4426950408889634f)  // 1/sqrt(128) * log2(e)

#define BM 64
#define BN 128
#define NT (NN / BN)

// smem layout (bytes) — fp8 tiles
#define KS 144                              // K row: 128 fp8 + 16 pad
#define HTS 144                             // HT row: 128 fp8 + 16 pad
#define PSS 144                             // P/Q row: 128 fp8 + 16 pad
#define KBYTES (128 * KS)                   // 18432
#define HTBYTES (256 * HTS)                 // 36864
#define PBYTES (64 * PSS)                   // 9216
#define OFF_K 0                             // 2 stages
#define OFF_HT (2 * KBYTES)                 // 36864, 2 stages
#define OFF_P (OFF_HT + 2 * HTBYTES)        // 110592 (Q staging aliases in prologue)
#define OFF_L (OFF_P + PBYTES)              // 119808
#define ATTN_SMEM (OFF_L + 1024)            // 120832

// device-global scratch (allocation-guard safe)
__device__ uint8_t g_Qf[NN * DH];           // Q*QSCALE, e4m3
__device__ uint8_t g_Kf[NN * DH];           // K, e4m3
__device__ uint8_t g_HfT[(size_t)TT * NN];  // H transposed, e4m3

// ===========================================================================
// helpers
// ===========================================================================
__device__ __forceinline__ uint32_t smem_u32(const void* p) {
    uint32_t a;
    asm("{ .reg .u64 t; cvta.to.shared.u64 t, %1; cvt.u32.u64 %0, t; }"
        : "=r"(a) : "l"(p));
    return a;
}
__device__ __forceinline__ void ldsm_x4(uint32_t& r0, uint32_t& r1,
                                        uint32_t& r2, uint32_t& r3, uint32_t a) {
    asm volatile("ldmatrix.sync.aligned.m8n8.x4.shared.b16 {%0,%1,%2,%3}, [%4];"
                 : "=r"(r0), "=r"(r1), "=r"(r2), "=r"(r3) : "r"(a));
}
// fp8 e4m3 MMA, K=32: A 4 regs, B 2 regs, C f32x4
__device__ __forceinline__ void mma_fp8(float* d, const uint32_t* a,
                                        uint32_t b0, uint32_t b1) {
    asm volatile("mma.sync.aligned.m16n8k32.row.col.f32.e4m3.e4m3.f32 "
                 "{%0,%1,%2,%3},{%4,%5,%6,%7},{%8,%9},{%0,%1,%2,%3};"
                 : "+f"(d[0]), "+f"(d[1]), "+f"(d[2]), "+f"(d[3])
                 : "r"(a[0]), "r"(a[1]), "r"(a[2]), "r"(a[3]), "r"(b0), "r"(b1));
}
__device__ __forceinline__ void cp16(uint32_t dst, const void* src) {
    asm volatile("cp.async.cg.shared.global [%0], [%1], 16;"
                 :: "r"(dst), "l"(src) : "memory");
}
__device__ __forceinline__ void cp_commit() {
    asm volatile("cp.async.commit_group;" ::: "memory");
}
__device__ __forceinline__ void cp_wait0() {
    asm volatile("cp.async.wait_group 0;" ::: "memory");
}
__device__ __forceinline__ float ex2f(float x) {
    float y;
    asm("ex2.approx.f32 %0, %1;" : "=f"(y) : "f"(x));
    return y;
}
// pack two floats -> e4m3x2 (low byte = lo)
__device__ __forceinline__ uint16_t packf8(float lo, float hi) {
    uint16_t r;
    asm("cvt.rn.satfinite.e4m3x2.f32 %0, %1, %2;" : "=h"(r) : "f"(hi), "f"(lo));
    return r;
}
__device__ __forceinline__ void bar_grp(int id) {
    asm volatile("bar.sync %0, %1;" :: "r"(id), "r"(128) : "memory");
}

// ===========================================================================
// Kernel 1: Q = (H Wq + bq)*QSCALE -> e4m3 ; K = H Wk + bk -> e4m3 (2 CTA/SM)
// ===========================================================================
__global__ void __launch_bounds__(256, 2)
qk_kernel(const float* __restrict__ H,
          const float* __restrict__ Wq, const float* __restrict__ bq,
          const float* __restrict__ Wk, const float* __restrict__ bk) {
    __shared__ float HsT[32 * 129];
    __shared__ float Ws[32 * 128];

    const float* W = blockIdx.y ? Wk : Wq;
    const float* b = blockIdx.y ? bk : bq;
    uint8_t* outp  = blockIdx.y ? g_Kf : g_Qf;
    const float osc = blockIdx.y ? 1.0f : QSCALE;

    const int tid = threadIdx.x;
    const int ty = tid >> 4, tx = tid & 15;
    const int row0 = blockIdx.x * 128;

    float acc[8][8];
    #pragma unroll
    for (int i = 0; i < 8; i++)
        #pragma unroll
        for (int j = 0; j < 8; j++) acc[i][j] = 0.f;

    for (int kc = 0; kc < TT; kc += 32) {
        __syncthreads();
        #pragma unroll
        for (int idx = tid; idx < 128 * 32; idx += 256) {
            int r = idx >> 5, k = idx & 31;
            HsT[k * 129 + r] = H[(size_t)(row0 + r) * TT + kc + k];
        }
        #pragma unroll
        for (int idx = tid; idx < 32 * 128; idx += 256) {
            int k = idx >> 7, c = idx & 127;
            Ws[k * 128 + c] = W[(size_t)(kc + k) * DH + c];
        }
        __syncthreads();
        #pragma unroll 4
        for (int k = 0; k < 32; k++) {
            float h[8], w[8];
            #pragma unroll
            for (int i = 0; i < 8; i++) h[i] = HsT[k * 129 + ty * 8 + i];
            float4 w0 = *(const float4*)&Ws[k * 128 + tx * 8];
            float4 w1 = *(const float4*)&Ws[k * 128 + tx * 8 + 4];
            w[0]=w0.x; w[1]=w0.y; w[2]=w0.z; w[3]=w0.w;
            w[4]=w1.x; w[5]=w1.y; w[6]=w1.z; w[7]=w1.w;
            #pragma unroll
            for (int i = 0; i < 8; i++)
                #pragma unroll
                for (int j = 0; j < 8; j++)
                    acc[i][j] += h[i] * w[j];
        }
    }

    float bb[8];
    {
        float4 b0 = *(const float4*)&b[tx * 8];
        float4 b1 = *(const float4*)&b[tx * 8 + 4];
        bb[0]=b0.x; bb[1]=b0.y; bb[2]=b0.z; bb[3]=b0.w;
        bb[4]=b1.x; bb[5]=b1.y; bb[6]=b1.z; bb[7]=b1.w;
    }
    #pragma unroll
    for (int i = 0; i < 8; i++) {
        int r = row0 + ty * 8 + i;
        float v[8];
        #pragma unroll
        for (int j = 0; j < 8; j++) v[j] = (acc[i][j] + bb[j]) * osc;
        uint32_t lo = (uint32_t)packf8(v[0], v[1]) | ((uint32_t)packf8(v[2], v[3]) << 16);
        uint32_t hi = (uint32_t)packf8(v[4], v[5]) | ((uint32_t)packf8(v[6], v[7]) << 16);
        uint2 o; o.x = lo; o.y = hi;
        *(uint2*)&outp[(size_t)r * DH + tx * 8] = o;
    }
}

// ===========================================================================
// Kernel 2: H -> Hᵀ e4m3  (g_HfT[c][n])
// ===========================================================================
__global__ __launch_bounds__(256)
void ht_kernel(const float* __restrict__ H) {
    __shared__ float t[32][33];
    int bx = blockIdx.x * 32;   // n
    int by = blockIdx.y * 32;   // c
    int x = threadIdx.x, y = threadIdx.y;
    #pragma unroll
    for (int i = 0; i < 32; i += 8)
        t[y + i][x] = H[(size_t)(bx + y + i) * TT + by + x];
    __syncthreads();
    #pragma unroll
    for (int i = 0; i < 32; i += 8) {
        uint16_t r = packf8(t[x][y + i], 0.f);
        g_HfT[(size_t)(by + y + i) * NN + bx + x] = (uint8_t)(r & 0xff);
    }
}

// ===========================================================================
// Kernel 3: flash attention, all-fp8 mma (m16n8k32).
// 8 warps: wr = wid>>2 (32 q-rows), wq = wid&3
// (MMA1: 32-key slice; MMA2: 64-col slice over full 128 keys).
// ===========================================================================
__device__ __forceinline__ void issue_tile(uint32_t sb, int tid, int k0, int stage) {
    {   // K tile: 128 keys x 128 fp8
        const uint8_t* src = g_Kf + (size_t)k0 * DH;
        uint32_t dstb = sb + OFF_K + stage * KBYTES;
        #pragma unroll
        for (int i = tid; i < 1024; i += 256) {
            int r = i >> 3, c = i & 7;
            cp16(dstb + r * KS + c * 16, src + r * 128 + c * 16);
        }
    }
    {   // HT tile: 256 cols x 128 keys fp8
        uint32_t dstb = sb + OFF_HT + stage * HTBYTES;
        #pragma unroll
        for (int i = tid; i < 2048; i += 256) {
            int r = i >> 3, c = i & 7;
            cp16(dstb + r * HTS + c * 16, g_HfT + (size_t)r * NN + k0 + c * 16);
        }
    }
}

__global__ __launch_bounds__(256, 1)
void attn11_kernel(const float* __restrict__ H, float* __restrict__ out) {
    extern __shared__ char sm[];
    const uint32_t sb = smem_u32(sm);
    const int tid = threadIdx.x;
    const int wid = tid >> 5, lane = tid & 31;
    const int wr = wid >> 2, wq = wid & 3;
    const int g = lane >> 2, t = lane & 3;
    const int bl = lane >> 3, rl = lane & 7;
    const int q0 = blockIdx.x * BM;

    // prologue: tile 0 + Q (into P region) in one cp.async group
    issue_tile(sb, tid, 0, 0);
    {
        const uint8_t* src = g_Qf + (size_t)q0 * DH;
        #pragma unroll
        for (int i = tid; i < 512; i += 256) {
            int r = i >> 3, c = i & 7;
            cp16(sb + OFF_P + r * PSS + c * 16, src + r * 128 + c * 16);
        }
    }
    cp_commit();
    cp_wait0();
    __syncthreads();

    // persistent Q A-frags: 2 m-blocks x 4 k32-steps
    uint32_t aq[2][4][4];
    #pragma unroll
    for (int mb = 0; mb < 2; mb++) {
        int m = wr * 32 + mb * 16 + rl + ((bl & 1) ? 8 : 0);
        #pragma unroll
        for (int s = 0; s < 4; s++) {
            uint32_t addr = sb + OFF_P + m * PSS + s * 32 + ((bl & 2) ? 16 : 0);
            ldsm_x4(aq[mb][s][0], aq[mb][s][1], aq[mb][s][2], aq[mb][s][3], addr);
        }
    }
    __syncthreads();   // Q reads done before P overwrites region

    float oacc[16][4];
    #pragma unroll
    for (int i = 0; i < 16; i++)
        #pragma unroll
        for (int j = 0; j < 4; j++) oacc[i][j] = 0.f;
    float lsum[4] = {0.f, 0.f, 0.f, 0.f};
    const int diag_kt = q0 >> 7;

    const int nrowb = wq * 32 + rl + ((bl & 2) ? 8 : 0);   // MMA1 B key row
    const int kcb = (bl & 1) ? 16 : 0;                     // MMA1 B k-byte off
    const int am = rl + ((bl & 1) ? 8 : 0);                // MMA2 A row comp
    const int akc = (bl & 2) ? 16 : 0;
    const int hrow = rl + ((bl & 2) ? 8 : 0);              // MMA2 B col-row comp
    const int hkc = (bl & 1) ? 16 : 0;

    for (int kt = 0; kt < NT; kt++) {
        const int k0 = kt * BN;
        const int cur = kt & 1;

        cp_wait0();
        __syncthreads();   // tile kt visible; prev-tile reads done everywhere

        if (kt + 1 < NT) {
            issue_tile(sb, tid, (kt + 1) * BN, cur ^ 1);
            cp_commit();
        }

        const uint32_t kbase  = sb + OFF_K + cur * KBYTES;
        const uint32_t htbase = sb + OFF_HT + cur * HTBYTES;

        // ---- MMA1: S[32, 32-key slice] = Q @ K^T  (4 k32-steps)
        float sacc[2][4][4];
        #pragma unroll
        for (int mb = 0; mb < 2; mb++)
            #pragma unroll
            for (int jj = 0; jj < 4; jj++)
                #pragma unroll
                for (int x = 0; x < 4; x++) sacc[mb][jj][x] = 0.f;

        #pragma unroll
        for (int s = 0; s < 4; s++) {
            #pragma unroll
            for (int nb = 0; nb < 2; nb++) {
                uint32_t addr = kbase + (nrowb + nb * 16) * KS + s * 32 + kcb;
                uint32_t b0, b1, b2, b3;
                ldsm_x4(b0, b1, b2, b3, addr);
                #pragma unroll
                for (int mb = 0; mb < 2; mb++) {
                    mma_fp8(sacc[mb][2 * nb],     aq[mb][s], b0, b1);
                    mma_fp8(sacc[mb][2 * nb + 1], aq[mb][s], b2, b3);
                }
            }
        }

        // ---- exp (ex2; scale folded), diag->1, row sums, publish P (e4m3)
        {
            const bool dt = (kt == diag_kt);
            #pragma unroll
            for (int mb = 0; mb < 2; mb++) {
                const int row0 = wr * 32 + mb * 16 + g;
                const int grow0 = q0 + row0, grow1 = grow0 + 8;
                #pragma unroll
                for (int jj = 0; jj < 4; jj++) {
                    int col = wq * 32 + jj * 8 + 2 * t;
                    int gcol = k0 + col;
                    float p0 = ex2f(sacc[mb][jj][0]);
                    float p1 = ex2f(sacc[mb][jj][1]);
                    float p2 = ex2f(sacc[mb][jj][2]);
                    float p3 = ex2f(sacc[mb][jj][3]);
                    if (dt) {   // diagonal logit forced to 0 -> p = 1 (exact in e4m3)
                        if (grow0 == gcol)     p0 = 1.f;
                        if (grow0 == gcol + 1) p1 = 1.f;
                        if (grow1 == gcol)     p2 = 1.f;
                        if (grow1 == gcol + 1) p3 = 1.f;
                    }
                    lsum[2 * mb]     += p0 + p1;
                    lsum[2 * mb + 1] += p2 + p3;
                    *(uint16_t*)(sm + OFF_P + row0 * PSS + col) = packf8(p0, p1);
                    *(uint16_t*)(sm + OFF_P + (row0 + 8) * PSS + col) = packf8(p2, p3);
                }
            }
        }
        bar_grp(1 + wr);   // P rows of this row-group visible to its 4 warps

        // ---- MMA2: O[32, 64-col slice] += P[32,128] @ H[128, 64-col slice]
        #pragma unroll
        for (int s2 = 0; s2 < 4; s2++) {
            uint32_t pa[2][4];
            #pragma unroll
            for (int mb = 0; mb < 2; mb++) {
                uint32_t addr = sb + OFF_P + (wr * 32 + mb * 16 + am) * PSS
                              + s2 * 32 + akc;
                ldsm_x4(pa[mb][0], pa[mb][1], pa[mb][2], pa[mb][3], addr);
            }
            #pragma unroll
            for (int jj = 0; jj < 4; jj++) {
                int nbase = wq * 64 + jj * 16;
                uint32_t addr = htbase + (nbase + hrow) * HTS + s2 * 32 + hkc;
                uint32_t b0, b1, b2, b3;
                ldsm_x4(b0, b1, b2, b3, addr);
                #pragma unroll
                for (int mb = 0; mb < 2; mb++) {
                    mma_fp8(oacc[mb * 8 + jj * 2],     pa[mb], b0, b1);
                    mma_fp8(oacc[mb * 8 + jj * 2 + 1], pa[mb], b2, b3);
                }
            }
        }
    }

    // ---- epilogue ----
    #pragma unroll
    for (int i = 0; i < 4; i++) {
        lsum[i] += __shfl_xor_sync(0xffffffffu, lsum[i], 1);
        lsum[i] += __shfl_xor_sync(0xffffffffu, lsum[i], 2);
    }
    float* Ls = (float*)(sm + OFF_L);
    __syncthreads();   // all MMA2 reads done before Ls region reuse is irrelevant; order barrier
    if (t == 0) {
        int r = wr * 32 + g;
        Ls[wq * 64 + r]      = lsum[0];
        Ls[wq * 64 + r + 8]  = lsum[1];
        Ls[wq * 64 + r + 16] = lsum[2];
        Ls[wq * 64 + r + 24] = lsum[3];
    }
    __syncthreads();

    #pragma unroll
    for (int mb = 0; mb < 2; mb++) {
        int row0 = wr * 32 + mb * 16 + g;
        float invA = 1.f / (Ls[row0] + Ls[64 + row0] + Ls[128 + row0] + Ls[192 + row0]);
        float invB = 1.f / (Ls[row0 + 8] + Ls[64 + row0 + 8] +
                            Ls[128 + row0 + 8] + Ls[192 + row0 + 8]);
        int grow0 = q0 + row0;
        #pragma unroll
        for (int jj = 0; jj < 4; jj++) {
            #pragma unroll
            for (int n8 = 0; n8 < 2; n8++) {
                int col = wq * 64 + jj * 16 + n8 * 8 + 2 * t;
                const float* oa = oacc[mb * 8 + jj * 2 + n8];
                float2 h0 = *(const float2*)(H + (size_t)grow0 * TT + col);
                float2 h1 = *(const float2*)(H + (size_t)(grow0 + 8) * TT + col);
                float2 o0, o1;
                o0.x = oa[0] * invA + h0.x;
                o0.y = oa[1] * invA + h0.y;
                o1.x = oa[2] * invB + h1.x;
                o1.y = oa[3] * invB + h1.y;
                *(float2*)(out + (size_t)grow0 * TT + col) = o0;
                *(float2*)(out + (size_t)(grow0 + 8) * TT + col) = o1;
            }
        }
    }
}

// ===========================================================================
extern "C" void kernel_launch(void* const* d_in, const int* in_sizes, int n_in,
                              void* d_out, int out_size) {
    const float* H  = (const float*)d_in[0];
    const float* Wq = (const float*)d_in[1];
    const float* bq = (const float*)d_in[2];
    const float* Wk = (const float*)d_in[3];
    const float* bk = (const float*)d_in[4];
    float* out = (float*)d_out;

    cudaFuncSetAttribute(attn11_kernel,
                         cudaFuncAttributeMaxDynamicSharedMemorySize, ATTN_SMEM);

    qk_kernel<<<dim3(NN / 128, 2), 256>>>(H, Wq, bq, Wk, bk);
    ht_kernel<<<dim3(NN / 32, TT / 32), dim3(32, 8)>>>(H);
    attn11_kernel<<<NN / BM, 256, ATTN_SMEM>>>(H, out);
}